// round 4
// baseline (speedup 1.0000x reference)
#include <cuda_runtime.h>

#define FULLMASK 0xffffffffu

// ---- problem constants ----
#define NATOMS 2048
#define NNEI   128
#define EMBED  128
#define HEADS  4
#define HDIM   32

typedef unsigned long long u64;

constexpr long long ATTN_OFF = (long long)NATOMS * NNEI * EMBED;  // 33,554,432

// ---- packed f32x2 helpers (Blackwell FFMA2 path; bit-exact fp32) ----
__device__ __forceinline__ u64 pack2(float x, float y) {
    u64 r; asm("mov.b64 %0, {%1, %2};" : "=l"(r) : "f"(x), "f"(y)); return r;
}
__device__ __forceinline__ float2 unpack2(u64 v) {
    float2 r; asm("mov.b64 {%0, %1}, %2;" : "=f"(r.x), "=f"(r.y) : "l"(v)); return r;
}
__device__ __forceinline__ void ffma2(u64& d, u64 a, u64 b) {
    asm("fma.rn.f32x2 %0, %1, %2, %0;" : "+l"(d) : "l"(a), "l"(b));
}

// ---- global scratch (static device arrays; no runtime alloc) ----
__device__ float bias_c[(long long)NATOMS * HEADS * 64 * 64];          // 134 MB
__device__ float qkv_g[(long long)NATOMS * 3 * HEADS * NNEI * HDIM];   // 50 MB
__device__ float o_g[(long long)NATOMS * HEADS * NNEI * HDIM];         // 17 MB

// =====================================================================
// K_bias: angle-MLP bias, symmetric pairs, 64x64 region only, FFMA2 MLP.
// =====================================================================
__global__ __launch_bounds__(256, 4)
void bias_kernel(const float* __restrict__ input_r,
                 const float* __restrict__ s_g,
                 const int*   __restrict__ atype,
                 const float* __restrict__ aew1,
                 const float* __restrict__ aeb1,
                 const float* __restrict__ aew2,
                 const float* __restrict__ aeb2,
                 const float* __restrict__ lng_g,
                 const float* __restrict__ lnb_g,
                 const float* __restrict__ ascale_g)
{
    __shared__ float r4[64 * 4];
    __shared__ float sS[64];
    __shared__ u64 wz[32 * 8];     // [u2][8]: w1 pairs f0..f5, b1 pair, pad
    __shared__ u64 w2p[32 * 4];    // [u2][4]: per-head w2 pairs
    __shared__ float st[4][16][17];

    const int n   = blockIdx.x;
    const int tid = threadIdx.x;
    const int ty  = tid >> 4;   // 0..15
    const int tx  = tid & 15;   // 0..15

    if (tid < 64) {
        const float* rp = input_r + ((size_t)n * NNEI + tid) * 3;
        *(float4*)&r4[tid * 4] = make_float4(rp[0], rp[1], rp[2], 0.f);
        sS[tid] = s_g[(size_t)n * NNEI + tid];
    } else if (tid >= 128 && tid < 160) {
        int u2 = tid - 128;                    // 0..31
        #pragma unroll
        for (int f = 0; f < 6; ++f)
            wz[u2 * 8 + f] = *(const u64*)(aew1 + f * 64 + 2 * u2);
        wz[u2 * 8 + 6] = *(const u64*)(aeb1 + 2 * u2);
        wz[u2 * 8 + 7] = 0ull;
        #pragma unroll
        for (int h = 0; h < 4; ++h)
            w2p[u2 * 4 + h] = pack2(aew2[(2 * u2) * 4 + h], aew2[(2 * u2 + 1) * 4 + h]);
    }

    int at = atype[n];
    int kval = (at == 0) ? 32 : (at == 1) ? 48 : 64;
    float asc = ascale_g[0];
    float b2r[4], lgr[4], lbr[4];
    #pragma unroll
    for (int i = 0; i < 4; ++i) { b2r[i] = aeb2[i]; lgr[i] = lng_g[i]; lbr[i] = lnb_g[i]; }
    __syncthreads();

    float* bg = bias_c + (long long)n * HEADS * 64 * 64;

    for (int ti = 0; ti < 4; ++ti) {
        for (int tj = ti; tj < 4; ++tj) {
            int qi = ti * 16 + ty;
            int kj = tj * 16 + tx;
            float4 rq = *(float4*)&r4[qi * 4];
            float4 rk = *(float4*)&r4[kj * 4];
            float cs = fminf(1.f, fmaxf(-1.f, rq.x * rk.x + rq.y * rk.y + rq.z * rk.z));
            float sn = sqrtf(1.f - cs * cs + 1e-8f);
            float sin2 = 2.f * sn * cs;
            float vm = __expf(2.f * (cs - 1.f));
            float sq = sS[qi], sk = sS[kj];
            float ssum = sq + sk, sdiff = fabsf(sq - sk);

            u64 cs2 = pack2(cs, cs),     sn2 = pack2(sn, sn);
            u64 si2 = pack2(sin2, sin2), vm2 = pack2(vm, vm);
            u64 su2 = pack2(ssum, ssum), sd2 = pack2(sdiff, sdiff);
            u64 a2[4] = {0ull, 0ull, 0ull, 0ull};

            #pragma unroll 4
            for (int u2 = 0; u2 < 32; ++u2) {
                const u64* w = &wz[u2 * 8];
                ulonglong2 w01 = *(const ulonglong2*)(w);
                ulonglong2 w23 = *(const ulonglong2*)(w + 2);
                ulonglong2 w45 = *(const ulonglong2*)(w + 4);
                ulonglong2 w6x = *(const ulonglong2*)(w + 6);
                u64 z2 = w6x.x;
                ffma2(z2, cs2, w01.x); ffma2(z2, sn2, w01.y);
                ffma2(z2, si2, w23.x); ffma2(z2, vm2, w23.y);
                ffma2(z2, su2, w45.x); ffma2(z2, sd2, w45.y);
                float2 z = unpack2(z2);
                float sl0 = __fdividef(z.x, 1.f + __expf(-z.x));
                float sl1 = __fdividef(z.y, 1.f + __expf(-z.y));
                u64 sl2 = pack2(sl0, sl1);
                ulonglong2 wA = *(const ulonglong2*)&w2p[u2 * 4];
                ulonglong2 wB = *(const ulonglong2*)&w2p[u2 * 4 + 2];
                ffma2(a2[0], sl2, wA.x); ffma2(a2[1], sl2, wA.y);
                ffma2(a2[2], sl2, wB.x); ffma2(a2[3], sl2, wB.y);
            }
            float2 p0 = unpack2(a2[0]), p1 = unpack2(a2[1]);
            float2 p2 = unpack2(a2[2]), p3 = unpack2(a2[3]);
            float a0 = b2r[0] + p0.x + p0.y;
            float a1 = b2r[1] + p1.x + p1.y;
            float a2s = b2r[2] + p2.x + p2.y;
            float a3 = b2r[3] + p3.x + p3.y;

            float mu = 0.25f * (a0 + a1 + a2s + a3);
            float d0 = a0 - mu, d1 = a1 - mu, d2 = a2s - mu, d3 = a3 - mu;
            float var = 0.25f * (d0 * d0 + d1 * d1 + d2 * d2 + d3 * d3);
            float rs = rsqrtf(var + 1e-5f);
            float mscale = ((qi < kval) && (kj < kval)) ? asc : 0.f;
            float v0 = (d0 * rs * lgr[0] + lbr[0]) * mscale;
            float v1 = (d1 * rs * lgr[1] + lbr[1]) * mscale;
            float v2 = (d2 * rs * lgr[2] + lbr[2]) * mscale;
            float v3 = (d3 * rs * lgr[3] + lbr[3]) * mscale;

            bg[(0 * 64 + qi) * 64 + kj] = v0;
            bg[(1 * 64 + qi) * 64 + kj] = v1;
            bg[(2 * 64 + qi) * 64 + kj] = v2;
            bg[(3 * 64 + qi) * 64 + kj] = v3;

            if (ti != tj) {
                st[0][ty][tx] = v0;
                st[1][ty][tx] = v1;
                st[2][ty][tx] = v2;
                st[3][ty][tx] = v3;
                __syncthreads();
                int qm = tj * 16 + ty;
                int km = ti * 16 + tx;
                #pragma unroll
                for (int h = 0; h < 4; ++h)
                    bg[(h * 64 + qm) * 64 + km] = st[h][tx][ty];
                __syncthreads();
            }
        }
    }
}

// =====================================================================
// K_qkv: per-atom GEMM via FFMA2. a-tile stored duplicated (x,x) as u64.
// =====================================================================
__global__ __launch_bounds__(256, 2)
void qkv_kernel(const float* __restrict__ query,
                const float* __restrict__ w_in,
                const float* __restrict__ b_in)
{
    __shared__ u64   at2[128 * 16];  // query tile, duplicated pairs [i][ee], 16KB
    __shared__ float bt[16 * 128];   // w_in tile [ee][j], 8KB

    const int n   = blockIdx.x;
    const int tid = threadIdx.x;
    const int tr  = tid >> 4;    // 0..15
    const int tc  = tid & 15;    // 0..15

    const float* gq = query + (size_t)n * NNEI * EMBED;

    for (int c = 0; c < 3; ++c) {
        u64 acc2[8][4];
        #pragma unroll
        for (int r = 0; r < 8; ++r)
            #pragma unroll
            for (int cc = 0; cc < 4; ++cc) acc2[r][cc] = 0ull;

        for (int e0 = 0; e0 < 128; e0 += 16) {
            __syncthreads();
            #pragma unroll
            for (int it = 0; it < 2; ++it) {
                int idx = it * 256 + tid;
                int i = idx >> 2, d4 = idx & 3;
                float4 v = *(const float4*)(gq + i * 128 + e0 + d4 * 4);
                ulonglong2 u0, u1;
                u0.x = pack2(v.x, v.x); u0.y = pack2(v.y, v.y);
                u1.x = pack2(v.z, v.z); u1.y = pack2(v.w, v.w);
                *(ulonglong2*)&at2[i * 16 + d4 * 4]     = u0;
                *(ulonglong2*)&at2[i * 16 + d4 * 4 + 2] = u1;
            }
            #pragma unroll
            for (int it = 0; it < 2; ++it) {
                int idx = it * 256 + tid;
                int ee = idx >> 5, j4 = idx & 31;
                *(float4*)&bt[ee * 128 + j4 * 4] =
                    *(const float4*)(w_in + (e0 + ee) * 384 + c * 128 + j4 * 4);
            }
            __syncthreads();
            #pragma unroll 4
            for (int ee = 0; ee < 16; ++ee) {
                u64 aa[8];
                #pragma unroll
                for (int r = 0; r < 8; ++r)
                    aa[r] = at2[(tr * 8 + r) * 16 + ee];    // LDS.64 broadcast
                ulonglong2 b01 = *(const ulonglong2*)&bt[ee * 128 + tc * 8];
                ulonglong2 b23 = *(const ulonglong2*)&bt[ee * 128 + tc * 8 + 4];
                #pragma unroll
                for (int r = 0; r < 8; ++r) {
                    ffma2(acc2[r][0], aa[r], b01.x);
                    ffma2(acc2[r][1], aa[r], b01.y);
                    ffma2(acc2[r][2], aa[r], b23.x);
                    ffma2(acc2[r][3], aa[r], b23.y);
                }
            }
        }
        int h  = tc >> 2;
        int d0 = (tc & 3) * 8;
        float bias8[8];
        #pragma unroll
        for (int cc = 0; cc < 8; ++cc) bias8[cc] = b_in[c * 128 + tc * 8 + cc];
        float* dst = qkv_g + ((long long)(n * 3 + c) * 4 + h) * 4096;
        #pragma unroll
        for (int r = 0; r < 8; ++r) {
            int i = tr * 8 + r;
            float2 q0 = unpack2(acc2[r][0]), q1 = unpack2(acc2[r][1]);
            float2 q2 = unpack2(acc2[r][2]), q3 = unpack2(acc2[r][3]);
            *(float4*)&dst[i * 32 + d0] =
                make_float4(q0.x + bias8[0], q0.y + bias8[1],
                            q1.x + bias8[2], q1.y + bias8[3]);
            *(float4*)&dst[i * 32 + d0 + 4] =
                make_float4(q2.x + bias8[4], q2.y + bias8[5],
                            q3.x + bias8[6], q3.y + bias8[7]);
        }
    }
}

// =====================================================================
// K_attn: per-(atom,head). 128 threads, ~60KB smem, 3 CTAs/SM. FFMA2.
// =====================================================================
constexpr int AOFF_Q  = 0;                  // [128][32]
constexpr int AOFF_K  = 4096;               // [128][36]
constexpr int AOFF_V  = 8704;               // [128][32]
constexpr int AOFF_AT = 12800;              // attn tile [16][136]
constexpr int AOFF_SW = 14976;              // [128]
constexpr int ATTN_SMEM_FLOATS = 15104;
constexpr size_t ATTN_SMEM_BYTES = (size_t)ATTN_SMEM_FLOATS * 4;  // 60,416

__global__ __launch_bounds__(128, 3)
void attn_kernel(const float* __restrict__ sw_g,
                 float* __restrict__ out)
{
    extern __shared__ float sm[];
    const int b    = blockIdx.x;
    const int n    = b >> 2;
    const int h    = b & 3;
    const int tid  = threadIdx.x;
    const int lane = tid & 31;
    const int wid  = tid >> 5;    // 0..3

    const float* qsrc = qkv_g + ((long long)(n * 3 + 0) * 4 + h) * 4096;
    const float* ksrc = qkv_g + ((long long)(n * 3 + 1) * 4 + h) * 4096;
    const float* vsrc = qkv_g + ((long long)(n * 3 + 2) * 4 + h) * 4096;
    #pragma unroll
    for (int it = 0; it < 8; ++it) {
        int idx = it * 128 + tid;
        int i = idx >> 3, d4 = idx & 7;
        float4 qv4 = *(const float4*)(qsrc + idx * 4);
        float4 kv4 = *(const float4*)(ksrc + idx * 4);
        float4 vv4 = *(const float4*)(vsrc + idx * 4);
        *(float4*)&sm[AOFF_Q + i * 32 + d4 * 4] = qv4;
        *(float4*)&sm[AOFF_K + i * 36 + d4 * 4] = kv4;
        *(float4*)&sm[AOFF_V + i * 32 + d4 * 4] = vv4;
    }
    if (tid < 128) sm[AOFF_SW + tid] = sw_g[(size_t)n * NNEI + tid];
    __syncthreads();

    for (int it = 0; it < 96; ++it) {
        int vec = it * 4 + wid;
        int t = vec >> 7, row = vec & 127;
        int off = (t == 0) ? (AOFF_Q + row * 32)
                : (t == 1) ? (AOFF_K + row * 36)
                           : (AOFF_V + row * 32);
        float x  = sm[off + lane];
        float ss = x * x;
        #pragma unroll
        for (int o = 16; o > 0; o >>= 1) ss += __shfl_xor_sync(FULLMASK, ss, o);
        float inv = 1.0f / fmaxf(sqrtf(ss), 1e-12f);
        if (t == 0) inv *= 0.17677669529663689f;
        sm[off + lane] = x * inv;
    }

    const float* bgn = bias_c + (long long)(n * 4 + h) * 64 * 64;

    for (int q0 = 0; q0 < 128; q0 += 16) {
        __syncthreads();
        #pragma unroll
        for (int rr = 0; rr < 4; ++rr) {
            int lr = wid * 4 + rr;
            int qi = q0 + lr;
            float bias0 = 0.f, bias1 = 0.f;
            if (qi < 64) {
                bias0 = bgn[qi * 64 + lane];
                bias1 = bgn[qi * 64 + 32 + lane];
            }
            const u64* qp = (const u64*)&sm[AOFF_Q + qi * 32];
            u64 qr_[16];
            #pragma unroll
            for (int i = 0; i < 16; ++i) qr_[i] = qp[i];
            float swq = sm[AOFF_SW + qi];
            float t[4], swk[4];
            #pragma unroll
            for (int rep = 0; rep < 4; ++rep) {
                int kj = rep * 32 + lane;
                const u64* kp = (const u64*)&sm[AOFF_K + kj * 36];
                u64 d0 = 0ull, d1 = 0ull, d2 = 0ull, d3 = 0ull;
                #pragma unroll
                for (int i = 0; i < 4; ++i) {
                    ffma2(d0, qr_[i * 4 + 0], kp[i * 4 + 0]);
                    ffma2(d1, qr_[i * 4 + 1], kp[i * 4 + 1]);
                    ffma2(d2, qr_[i * 4 + 2], kp[i * 4 + 2]);
                    ffma2(d3, qr_[i * 4 + 3], kp[i * 4 + 3]);
                }
                float2 f0 = unpack2(d0), f1 = unpack2(d1);
                float2 f2 = unpack2(d2), f3 = unpack2(d3);
                float dot = ((f0.x + f0.y) + (f1.x + f1.y))
                          + ((f2.x + f2.y) + (f3.x + f3.y));
                float bias = (rep == 0) ? bias0 : (rep == 1) ? bias1 : 0.f;
                swk[rep] = sm[AOFF_SW + kj];
                t[rep] = (dot + bias + 20.f) * swq * swk[rep] - 20.f;
            }
            float mx = fmaxf(fmaxf(t[0], t[1]), fmaxf(t[2], t[3]));
            #pragma unroll
            for (int o = 16; o > 0; o >>= 1)
                mx = fmaxf(mx, __shfl_xor_sync(FULLMASK, mx, o));
            float e[4]; float ssm = 0.f;
            #pragma unroll
            for (int rep = 0; rep < 4; ++rep) { e[rep] = __expf(t[rep] - mx); ssm += e[rep]; }
            #pragma unroll
            for (int o = 16; o > 0; o >>= 1) ssm += __shfl_xor_sync(FULLMASK, ssm, o);
            float inv = __fdividef(1.f, ssm);

            float* ab = &sm[AOFF_AT + lr * 136];
            float* ga = out + ATTN_OFF + (((long long)n * 4 + h) * 128 + qi) * 128;
            #pragma unroll
            for (int rep = 0; rep < 4; ++rep) {
                float a = e[rep] * inv * swq * swk[rep];
                ab[rep * 32 + lane] = a;
                ga[rep * 32 + lane] = a;
            }
        }
        __syncthreads();

        // o-gemm: 16x32 tile, 1x4 micro via FFMA2 (4 partial accumulators)
        {
            int r  = tid >> 3;
            int c0 = (tid & 7) * 4;
            u64 accA0 = 0ull, accA1 = 0ull, accB0 = 0ull, accB1 = 0ull;
            const float* ab = &sm[AOFF_AT + r * 136];
            const float* vb = &sm[AOFF_V];
            #pragma unroll 4
            for (int k0 = 0; k0 < 128; k0 += 8) {
                float4 a4 = *(const float4*)&ab[k0];
                float4 a4b = *(const float4*)&ab[k0 + 4];
                ulonglong2 v0 = *(const ulonglong2*)&vb[(k0 + 0) * 32 + c0];
                ulonglong2 v1 = *(const ulonglong2*)&vb[(k0 + 1) * 32 + c0];
                ulonglong2 v2 = *(const ulonglong2*)&vb[(k0 + 2) * 32 + c0];
                ulonglong2 v3 = *(const ulonglong2*)&vb[(k0 + 3) * 32 + c0];
                ulonglong2 v4 = *(const ulonglong2*)&vb[(k0 + 4) * 32 + c0];
                ulonglong2 v5 = *(const ulonglong2*)&vb[(k0 + 5) * 32 + c0];
                ulonglong2 v6 = *(const ulonglong2*)&vb[(k0 + 6) * 32 + c0];
                ulonglong2 v7 = *(const ulonglong2*)&vb[(k0 + 7) * 32 + c0];
                u64 p;
                p = pack2(a4.x,  a4.x);  ffma2(accA0, p, v0.x); ffma2(accA1, p, v0.y);
                p = pack2(a4.y,  a4.y);  ffma2(accB0, p, v1.x); ffma2(accB1, p, v1.y);
                p = pack2(a4.z,  a4.z);  ffma2(accA0, p, v2.x); ffma2(accA1, p, v2.y);
                p = pack2(a4.w,  a4.w);  ffma2(accB0, p, v3.x); ffma2(accB1, p, v3.y);
                p = pack2(a4b.x, a4b.x); ffma2(accA0, p, v4.x); ffma2(accA1, p, v4.y);
                p = pack2(a4b.y, a4b.y); ffma2(accB0, p, v5.x); ffma2(accB1, p, v5.y);
                p = pack2(a4b.z, a4b.z); ffma2(accA0, p, v6.x); ffma2(accA1, p, v6.y);
                p = pack2(a4b.w, a4b.w); ffma2(accB0, p, v7.x); ffma2(accB1, p, v7.y);
            }
            float2 rA0 = unpack2(accA0), rB0 = unpack2(accB0);
            float2 rA1 = unpack2(accA1), rB1 = unpack2(accB1);
            *(float4*)&o_g[(((long long)n * 4 + h) * 128 + q0 + r) * 32 + c0] =
                make_float4(rA0.x + rB0.x, rA0.y + rB0.y, rA1.x + rB1.x, rA1.y + rB1.y);
        }
    }
}

// =====================================================================
// K_out: output = o @ w_out + b_out via FFMA2.
// =====================================================================
__global__ __launch_bounds__(256, 2)
void out_kernel(const float* __restrict__ w_out,
                const float* __restrict__ b_out,
                float* __restrict__ out)
{
    __shared__ float wt[32 * 128];   // 16KB
    __shared__ u64   oh2[128 * 32];  // o tile duplicated pairs, 32KB

    const int n   = blockIdx.x;
    const int tid = threadIdx.x;
    const int tr  = tid >> 4;
    const int tc  = tid & 15;

    u64 acc2[8][4];
    #pragma unroll
    for (int r = 0; r < 8; ++r)
        #pragma unroll
        for (int cc = 0; cc < 4; ++cc) acc2[r][cc] = 0ull;

    for (int h = 0; h < 4; ++h) {
        __syncthreads();
        #pragma unroll
        for (int it = 0; it < 4; ++it) {
            int idx = it * 256 + tid;
            int kk = idx >> 5, j4 = idx & 31;
            *(float4*)&wt[kk * 128 + j4 * 4] =
                *(const float4*)(w_out + (h * 32 + kk) * 128 + j4 * 4);
            int i = idx >> 3, d4 = idx & 7;
            float4 v = *(const float4*)(o_g + (((long long)n * 4 + h) * 128 + i) * 32 + d4 * 4);
            ulonglong2 u0, u1;
            u0.x = pack2(v.x, v.x); u0.y = pack2(v.y, v.y);
            u1.x = pack2(v.z, v.z); u1.y = pack2(v.w, v.w);
            *(ulonglong2*)&oh2[i * 32 + d4 * 4]     = u0;
            *(ulonglong2*)&oh2[i * 32 + d4 * 4 + 2] = u1;
        }
        __syncthreads();
        #pragma unroll 4
        for (int kk = 0; kk < 32; ++kk) {
            u64 aa[8];
            #pragma unroll
            for (int r = 0; r < 8; ++r)
                aa[r] = oh2[(tr * 8 + r) * 32 + kk];
            ulonglong2 b01 = *(const ulonglong2*)&wt[kk * 128 + tc * 8];
            ulonglong2 b23 = *(const ulonglong2*)&wt[kk * 128 + tc * 8 + 4];
            #pragma unroll
            for (int r = 0; r < 8; ++r) {
                ffma2(acc2[r][0], aa[r], b01.x);
                ffma2(acc2[r][1], aa[r], b01.y);
                ffma2(acc2[r][2], aa[r], b23.x);
                ffma2(acc2[r][3], aa[r], b23.y);
            }
        }
    }
    float bo[8];
    #pragma unroll
    for (int cc = 0; cc < 8; ++cc) bo[cc] = b_out[tc * 8 + cc];
    #pragma unroll
    for (int r = 0; r < 8; ++r) {
        float2 q0 = unpack2(acc2[r][0]), q1 = unpack2(acc2[r][1]);
        float2 q2 = unpack2(acc2[r][2]), q3 = unpack2(acc2[r][3]);
        float* go = out + ((long long)n * 128 + tr * 8 + r) * 128 + tc * 8;
        *(float4*)go = make_float4(q0.x + bo[0], q0.y + bo[1],
                                   q1.x + bo[2], q1.y + bo[3]);
        *(float4*)(go + 4) = make_float4(q2.x + bo[4], q2.y + bo[5],
                                         q3.x + bo[6], q3.y + bo[7]);
    }
}

extern "C" void kernel_launch(void* const* d_in, const int* in_sizes, int n_in,
                              void* d_out, int out_size)
{
    const float* query   = (const float*)d_in[0];
    // d_in[1] = nei_mask (all True) — unused
    const float* input_r = (const float*)d_in[2];
    const float* sw      = (const float*)d_in[3];
    const float* s       = (const float*)d_in[4];
    const int*   atype   = (const int*)  d_in[5];
    const float* w_in    = (const float*)d_in[6];
    const float* b_in    = (const float*)d_in[7];
    const float* w_out   = (const float*)d_in[8];
    const float* b_out   = (const float*)d_in[9];
    const float* aew1    = (const float*)d_in[10];
    const float* aeb1    = (const float*)d_in[11];
    const float* aew2    = (const float*)d_in[12];
    const float* aeb2    = (const float*)d_in[13];
    const float* lng     = (const float*)d_in[14];
    const float* lnb     = (const float*)d_in[15];
    const float* ascale  = (const float*)d_in[16];
    float* outp = (float*)d_out;

    bias_kernel<<<NATOMS, 256>>>(input_r, s, atype, aew1, aeb1, aew2, aeb2,
                                 lng, lnb, ascale);
    qkv_kernel<<<NATOMS, 256>>>(query, w_in, b_in);

    cudaFuncSetAttribute(attn_kernel, cudaFuncAttributeMaxDynamicSharedMemorySize,
                         (int)ATTN_SMEM_BYTES);
    attn_kernel<<<NATOMS * HEADS, 128, ATTN_SMEM_BYTES>>>(sw, outp);

    out_kernel<<<NATOMS, 256>>>(w_out, b_out, outp);
}

// round 5
// speedup vs baseline: 1.3535x; 1.3535x over previous
#include <cuda_runtime.h>
#include <cuda_bf16.h>

#define FULLMASK 0xffffffffu

// ---- problem constants ----
#define NATOMS 2048
#define NNEI   128
#define EMBED  128
#define HEADS  4
#define HDIM   32

typedef unsigned int u32;

constexpr long long ATTN_OFF = (long long)NATOMS * NNEI * EMBED;  // 33,554,432

// ---- global scratch (static device arrays; no runtime alloc) ----
__device__ float bias_c[(long long)NATOMS * HEADS * 64 * 64];          // 134 MB
__device__ float qkv_g[(long long)NATOMS * 3 * HEADS * NNEI * HDIM];   // 50 MB
__device__ float o_g[(long long)NATOMS * HEADS * NNEI * HDIM];         // 17 MB
// pre-split, pre-transposed weights: wt[c][n][k] = w_in[k][c*128+n]
__device__ __nv_bfloat16 wtin_h[3 * 128 * 128];
__device__ __nv_bfloat16 wtin_l[3 * 128 * 128];
// wo[n][k] = w_out[k][n]
__device__ __nv_bfloat16 wtout_h[128 * 128];
__device__ __nv_bfloat16 wtout_l[128 * 128];

// ---- mma.sync m16n8k16 bf16 ----
__device__ __forceinline__ void mma16816(float* c, const u32* a, u32 b0, u32 b1) {
    asm volatile(
        "mma.sync.aligned.m16n8k16.row.col.f32.bf16.bf16.f32 "
        "{%0,%1,%2,%3}, {%4,%5,%6,%7}, {%8,%9}, {%0,%1,%2,%3};\n"
        : "+f"(c[0]), "+f"(c[1]), "+f"(c[2]), "+f"(c[3])
        : "r"(a[0]), "r"(a[1]), "r"(a[2]), "r"(a[3]), "r"(b0), "r"(b1));
}

// =====================================================================
// K_prep: split+transpose weights into bf16 hi/lo (one-time, tiny).
// =====================================================================
__global__ void prep_kernel(const float* __restrict__ w_in,
                            const float* __restrict__ w_out)
{
    int idx = blockIdx.x * 256 + threadIdx.x;   // 65536 total
    if (idx < 3 * 128 * 128) {
        int c = idx >> 14, r = idx & 16383;
        int nn = r >> 7, k = r & 127;
        float v = w_in[k * 384 + c * 128 + nn];
        __nv_bfloat16 h = __float2bfloat16_rn(v);
        __nv_bfloat16 l = __float2bfloat16_rn(v - __bfloat162float(h));
        wtin_h[idx] = h;
        wtin_l[idx] = l;
    } else {
        int j = idx - 3 * 128 * 128;
        int nn = j >> 7, k = j & 127;
        float v = w_out[k * 128 + nn];
        __nv_bfloat16 h = __float2bfloat16_rn(v);
        __nv_bfloat16 l = __float2bfloat16_rn(v - __bfloat162float(h));
        wtout_h[j] = h;
        wtout_l[j] = l;
    }
}

// =====================================================================
// K_bias: angle-MLP bias, symmetric pairs, 64x64 region only (R3).
// =====================================================================
__global__ __launch_bounds__(256, 4)
void bias_kernel(const float* __restrict__ input_r,
                 const float* __restrict__ s_g,
                 const int*   __restrict__ atype,
                 const float* __restrict__ aew1,
                 const float* __restrict__ aeb1,
                 const float* __restrict__ aew2,
                 const float* __restrict__ aeb2,
                 const float* __restrict__ lng_g,
                 const float* __restrict__ lnb_g,
                 const float* __restrict__ ascale_g)
{
    __shared__ float r4[64 * 4];
    __shared__ float sS[64];
    __shared__ float w1a[256], w1b[256], w2s[256];
    __shared__ float st[4][16][17];

    const int n   = blockIdx.x;
    const int tid = threadIdx.x;
    const int ty  = tid >> 4;
    const int tx  = tid & 15;

    if (tid < 64) {
        const float* rp = input_r + ((size_t)n * NNEI + tid) * 3;
        *(float4*)&r4[tid * 4] = make_float4(rp[0], rp[1], rp[2], 0.f);
        sS[tid] = s_g[(size_t)n * NNEI + tid];
    } else if (tid >= 128 && tid < 192) {
        int u = tid - 128;
        *(float4*)&w1a[u * 4] =
            make_float4(aew1[u], aew1[64 + u], aew1[128 + u], aew1[192 + u]);
        *(float4*)&w1b[u * 4] =
            make_float4(aew1[256 + u], aew1[320 + u], aeb1[u], 0.f);
        *(float4*)&w2s[u * 4] = *(const float4*)(aew2 + u * 4);
    }

    int at = atype[n];
    int kval = (at == 0) ? 32 : (at == 1) ? 48 : 64;
    float asc = ascale_g[0];
    float b2r[4], lgr[4], lbr[4];
    #pragma unroll
    for (int i = 0; i < 4; ++i) { b2r[i] = aeb2[i]; lgr[i] = lng_g[i]; lbr[i] = lnb_g[i]; }
    __syncthreads();

    float* bg = bias_c + (long long)n * HEADS * 64 * 64;

    for (int ti = 0; ti < 4; ++ti) {
        for (int tj = ti; tj < 4; ++tj) {
            int qi = ti * 16 + ty;
            int kj = tj * 16 + tx;
            float4 rq = *(float4*)&r4[qi * 4];
            float4 rk = *(float4*)&r4[kj * 4];
            float cs = fminf(1.f, fmaxf(-1.f, rq.x * rk.x + rq.y * rk.y + rq.z * rk.z));
            float sn = sqrtf(1.f - cs * cs + 1e-8f);
            float sin2 = 2.f * sn * cs;
            float vm = __expf(2.f * (cs - 1.f));
            float sq = sS[qi], sk = sS[kj];
            float ssum = sq + sk, sdiff = fabsf(sq - sk);
            float a0 = 0.f, a1 = 0.f, a2 = 0.f, a3 = 0.f;
            #pragma unroll 8
            for (int u = 0; u < 64; ++u) {
                float4 wa = *(float4*)&w1a[u * 4];
                float4 wb = *(float4*)&w1b[u * 4];
                float z = wb.z;
                z = fmaf(cs,    wa.x, z);
                z = fmaf(sn,    wa.y, z);
                z = fmaf(sin2,  wa.z, z);
                z = fmaf(vm,    wa.w, z);
                z = fmaf(ssum,  wb.x, z);
                z = fmaf(sdiff, wb.y, z);
                float sl = __fdividef(z, 1.f + __expf(-z));   // silu
                float4 w2 = *(float4*)&w2s[u * 4];
                a0 = fmaf(sl, w2.x, a0);
                a1 = fmaf(sl, w2.y, a1);
                a2 = fmaf(sl, w2.z, a2);
                a3 = fmaf(sl, w2.w, a3);
            }
            a0 += b2r[0]; a1 += b2r[1]; a2 += b2r[2]; a3 += b2r[3];
            float mu = 0.25f * (a0 + a1 + a2 + a3);
            float d0 = a0 - mu, d1 = a1 - mu, d2 = a2 - mu, d3 = a3 - mu;
            float var = 0.25f * (d0 * d0 + d1 * d1 + d2 * d2 + d3 * d3);
            float rs = rsqrtf(var + 1e-5f);
            float mscale = ((qi < kval) && (kj < kval)) ? asc : 0.f;
            float v0 = (d0 * rs * lgr[0] + lbr[0]) * mscale;
            float v1 = (d1 * rs * lgr[1] + lbr[1]) * mscale;
            float v2 = (d2 * rs * lgr[2] + lbr[2]) * mscale;
            float v3 = (d3 * rs * lgr[3] + lbr[3]) * mscale;

            bg[(0 * 64 + qi) * 64 + kj] = v0;
            bg[(1 * 64 + qi) * 64 + kj] = v1;
            bg[(2 * 64 + qi) * 64 + kj] = v2;
            bg[(3 * 64 + qi) * 64 + kj] = v3;

            if (ti != tj) {
                st[0][ty][tx] = v0;
                st[1][ty][tx] = v1;
                st[2][ty][tx] = v2;
                st[3][ty][tx] = v3;
                __syncthreads();
                int qm = tj * 16 + ty;
                int km = ti * 16 + tx;
                #pragma unroll
                for (int h = 0; h < 4; ++h)
                    bg[(h * 64 + qm) * 64 + km] = st[h][tx][ty];
                __syncthreads();
            }
        }
    }
}

// =====================================================================
// K_qkv: per-atom [128x128]@[128x384] via mma.sync bf16 2-way split.
// smem: Ah/Al [128][136], Wh/Wl [128][136] bf16  (139,264 B)
// warp w: m-tiles {2*(w&3), 2*(w&3)+1}, n-tiles (w>>2)*8 .. +7 per chunk
// =====================================================================
constexpr int LDA = 136;  // bf16 row stride (68 words -> 4-bank shift, conflict-free frags)
constexpr size_t GEMM_SMEM_BYTES = (size_t)4 * 128 * LDA * 2;  // 139,264

__global__ __launch_bounds__(256, 1)
void qkv_kernel(const float* __restrict__ query,
                const float* __restrict__ b_in)
{
    extern __shared__ __nv_bfloat16 smb[];
    __nv_bfloat16* Ah = smb;
    __nv_bfloat16* Al = smb + 128 * LDA;
    __nv_bfloat16* Wh = smb + 2 * 128 * LDA;
    __nv_bfloat16* Wl = smb + 3 * 128 * LDA;

    const int n    = blockIdx.x;
    const int tid  = threadIdx.x;
    const int lane = tid & 31;
    const int wid  = tid >> 5;
    const int m2   = wid & 3;      // m-tile pair
    const int ng   = wid >> 2;     // n half
    const int mrow0 = m2 * 32;

    // ---- stage + split A (query rows) ----
    const float* gq = query + (size_t)n * NNEI * EMBED;
    #pragma unroll
    for (int it = 0; it < 16; ++it) {
        int idx = it * 256 + tid;            // 4096 float4
        int i = idx >> 5, e4 = (idx & 31) * 4;
        float4 v = *(const float4*)(gq + i * 128 + e4);
        __nv_bfloat16 h0 = __float2bfloat16_rn(v.x);
        __nv_bfloat16 h1 = __float2bfloat16_rn(v.y);
        __nv_bfloat16 h2 = __float2bfloat16_rn(v.z);
        __nv_bfloat16 h3 = __float2bfloat16_rn(v.w);
        *(__nv_bfloat162*)&Ah[i * LDA + e4]     = __halves2bfloat162(h0, h1);
        *(__nv_bfloat162*)&Ah[i * LDA + e4 + 2] = __halves2bfloat162(h2, h3);
        *(__nv_bfloat162*)&Al[i * LDA + e4] = __halves2bfloat162(
            __float2bfloat16_rn(v.x - __bfloat162float(h0)),
            __float2bfloat16_rn(v.y - __bfloat162float(h1)));
        *(__nv_bfloat162*)&Al[i * LDA + e4 + 2] = __halves2bfloat162(
            __float2bfloat16_rn(v.z - __bfloat162float(h2)),
            __float2bfloat16_rn(v.w - __bfloat162float(h3)));
    }

    const int r0 = lane >> 2;
    const int kp = (lane & 3) * 2;

    for (int c = 0; c < 3; ++c) {
        __syncthreads();
        // ---- stage W chunk (pre-split/transposed in global) ----
        const __nv_bfloat16* gwh = wtin_h + c * 16384;
        const __nv_bfloat16* gwl = wtin_l + c * 16384;
        #pragma unroll
        for (int it = 0; it < 8; ++it) {
            int idx = it * 256 + tid;        // 2048 x 8 bf16
            int nn = idx >> 4, k8 = (idx & 15) * 8;
            *(float4*)&Wh[nn * LDA + k8] = *(const float4*)&gwh[nn * 128 + k8];
            *(float4*)&Wl[nn * LDA + k8] = *(const float4*)&gwl[nn * 128 + k8];
        }
        __syncthreads();

        float acc[2][8][4];
        #pragma unroll
        for (int mi = 0; mi < 2; ++mi)
            #pragma unroll
            for (int nt = 0; nt < 8; ++nt)
                #pragma unroll
                for (int q = 0; q < 4; ++q) acc[mi][nt][q] = 0.f;

        #pragma unroll
        for (int k = 0; k < 8; ++k) {
            int k0 = k * 16 + kp;
            u32 ah[2][4], al[2][4];
            #pragma unroll
            for (int mi = 0; mi < 2; ++mi) {
                int r = mrow0 + mi * 16 + r0;
                ah[mi][0] = *(const u32*)&Ah[r * LDA + k0];
                ah[mi][1] = *(const u32*)&Ah[(r + 8) * LDA + k0];
                ah[mi][2] = *(const u32*)&Ah[r * LDA + k0 + 8];
                ah[mi][3] = *(const u32*)&Ah[(r + 8) * LDA + k0 + 8];
                al[mi][0] = *(const u32*)&Al[r * LDA + k0];
                al[mi][1] = *(const u32*)&Al[(r + 8) * LDA + k0];
                al[mi][2] = *(const u32*)&Al[r * LDA + k0 + 8];
                al[mi][3] = *(const u32*)&Al[(r + 8) * LDA + k0 + 8];
            }
            #pragma unroll
            for (int nt = 0; nt < 8; ++nt) {
                int ncol = ng * 64 + nt * 8 + r0;
                u32 bh0 = *(const u32*)&Wh[ncol * LDA + k0];
                u32 bh1 = *(const u32*)&Wh[ncol * LDA + k0 + 8];
                u32 bl0 = *(const u32*)&Wl[ncol * LDA + k0];
                u32 bl1 = *(const u32*)&Wl[ncol * LDA + k0 + 8];
                #pragma unroll
                for (int mi = 0; mi < 2; ++mi) {
                    mma16816(acc[mi][nt], ah[mi], bh0, bh1);
                    mma16816(acc[mi][nt], ah[mi], bl0, bl1);
                    mma16816(acc[mi][nt], al[mi], bh0, bh1);
                }
            }
        }

        // ---- epilogue: + b_in, scatter to head layout ----
        #pragma unroll
        for (int mi = 0; mi < 2; ++mi) {
            #pragma unroll
            for (int nt = 0; nt < 8; ++nt) {
                int gr = mrow0 + mi * 16 + r0;
                int gc = ng * 64 + nt * 8 + kp;
                int h  = gc >> 5, d = gc & 31;
                float bi0 = b_in[c * 128 + gc];
                float bi1 = b_in[c * 128 + gc + 1];
                float* dst = qkv_g + (((long long)n * 3 + c) * 4 + h) * 4096;
                *(float2*)&dst[gr * 32 + d] =
                    make_float2(acc[mi][nt][0] + bi0, acc[mi][nt][1] + bi1);
                *(float2*)&dst[(gr + 8) * 32 + d] =
                    make_float2(acc[mi][nt][2] + bi0, acc[mi][nt][3] + bi1);
            }
        }
    }
}

// =====================================================================
// K_attn: per-(atom,head). 128 threads, ~60KB smem, 3 CTAs/SM (R3).
// =====================================================================
constexpr int AOFF_Q  = 0;
constexpr int AOFF_K  = 4096;
constexpr int AOFF_V  = 8704;
constexpr int AOFF_AT = 12800;
constexpr int AOFF_SW = 14976;
constexpr int ATTN_SMEM_FLOATS = 15104;
constexpr size_t ATTN_SMEM_BYTES = (size_t)ATTN_SMEM_FLOATS * 4;  // 60,416

__global__ __launch_bounds__(128, 3)
void attn_kernel(const float* __restrict__ sw_g,
                 float* __restrict__ out)
{
    extern __shared__ float sm[];
    const int b    = blockIdx.x;
    const int n    = b >> 2;
    const int h    = b & 3;
    const int tid  = threadIdx.x;
    const int lane = tid & 31;
    const int wid  = tid >> 5;

    const float* qsrc = qkv_g + ((long long)(n * 3 + 0) * 4 + h) * 4096;
    const float* ksrc = qkv_g + ((long long)(n * 3 + 1) * 4 + h) * 4096;
    const float* vsrc = qkv_g + ((long long)(n * 3 + 2) * 4 + h) * 4096;
    #pragma unroll
    for (int it = 0; it < 8; ++it) {
        int idx = it * 128 + tid;
        int i = idx >> 3, d4 = idx & 7;
        float4 qv4 = *(const float4*)(qsrc + idx * 4);
        float4 kv4 = *(const float4*)(ksrc + idx * 4);
        float4 vv4 = *(const float4*)(vsrc + idx * 4);
        *(float4*)&sm[AOFF_Q + i * 32 + d4 * 4] = qv4;
        *(float4*)&sm[AOFF_K + i * 36 + d4 * 4] = kv4;
        *(float4*)&sm[AOFF_V + i * 32 + d4 * 4] = vv4;
    }
    if (tid < 128) sm[AOFF_SW + tid] = sw_g[(size_t)n * NNEI + tid];
    __syncthreads();

    for (int it = 0; it < 96; ++it) {
        int vec = it * 4 + wid;
        int t = vec >> 7, row = vec & 127;
        int off = (t == 0) ? (AOFF_Q + row * 32)
                : (t == 1) ? (AOFF_K + row * 36)
                           : (AOFF_V + row * 32);
        float x  = sm[off + lane];
        float ss = x * x;
        #pragma unroll
        for (int o = 16; o > 0; o >>= 1) ss += __shfl_xor_sync(FULLMASK, ss, o);
        float inv = 1.0f / fmaxf(sqrtf(ss), 1e-12f);
        if (t == 0) inv *= 0.17677669529663689f;
        sm[off + lane] = x * inv;
    }

    const float* bgn = bias_c + (long long)(n * 4 + h) * 64 * 64;

    for (int q0 = 0; q0 < 128; q0 += 16) {
        __syncthreads();
        #pragma unroll
        for (int rr = 0; rr < 4; ++rr) {
            int lr = wid * 4 + rr;
            int qi = q0 + lr;
            float bias0 = 0.f, bias1 = 0.f;
            if (qi < 64) {
                bias0 = bgn[qi * 64 + lane];
                bias1 = bgn[qi * 64 + 32 + lane];
            }
            const float* qrow = &sm[AOFF_Q + qi * 32];
            float4 qv[8];
            #pragma unroll
            for (int d4 = 0; d4 < 8; ++d4) qv[d4] = ((const float4*)qrow)[d4];
            float swq = sm[AOFF_SW + qi];
            float t[4], swk[4];
            #pragma unroll
            for (int rep = 0; rep < 4; ++rep) {
                int kj = rep * 32 + lane;
                const float* krow = &sm[AOFF_K + kj * 36];
                float dot = 0.f;
                #pragma unroll
                for (int d4 = 0; d4 < 8; ++d4) {
                    float4 kv = ((const float4*)krow)[d4];
                    dot = fmaf(qv[d4].x, kv.x, dot);
                    dot = fmaf(qv[d4].y, kv.y, dot);
                    dot = fmaf(qv[d4].z, kv.z, dot);
                    dot = fmaf(qv[d4].w, kv.w, dot);
                }
                float bias = (rep == 0) ? bias0 : (rep == 1) ? bias1 : 0.f;
                swk[rep] = sm[AOFF_SW + kj];
                t[rep] = (dot + bias + 20.f) * swq * swk[rep] - 20.f;
            }
            float mx = fmaxf(fmaxf(t[0], t[1]), fmaxf(t[2], t[3]));
            #pragma unroll
            for (int o = 16; o > 0; o >>= 1)
                mx = fmaxf(mx, __shfl_xor_sync(FULLMASK, mx, o));
            float e[4]; float ssm = 0.f;
            #pragma unroll
            for (int rep = 0; rep < 4; ++rep) { e[rep] = __expf(t[rep] - mx); ssm += e[rep]; }
            #pragma unroll
            for (int o = 16; o > 0; o >>= 1) ssm += __shfl_xor_sync(FULLMASK, ssm, o);
            float inv = __fdividef(1.f, ssm);

            float* ab = &sm[AOFF_AT + lr * 136];
            float* ga = out + ATTN_OFF + (((long long)n * 4 + h) * 128 + qi) * 128;
            #pragma unroll
            for (int rep = 0; rep < 4; ++rep) {
                float a = e[rep] * inv * swq * swk[rep];
                ab[rep * 32 + lane] = a;
                ga[rep * 32 + lane] = a;
            }
        }
        __syncthreads();

        {
            int r  = tid >> 3;
            int c0 = (tid & 7) * 4;
            float acc0 = 0.f, acc1 = 0.f, acc2 = 0.f, acc3 = 0.f;
            const float* ab = &sm[AOFF_AT + r * 136];
            const float* vb = &sm[AOFF_V];
            #pragma unroll 8
            for (int k0 = 0; k0 < 128; k0 += 4) {
                float4 a4 = *(const float4*)&ab[k0];
                float4 v0 = *(const float4*)&vb[(k0 + 0) * 32 + c0];
                float4 v1 = *(const float4*)&vb[(k0 + 1) * 32 + c0];
                float4 v2 = *(const float4*)&vb[(k0 + 2) * 32 + c0];
                float4 v3 = *(const float4*)&vb[(k0 + 3) * 32 + c0];
                acc0 = fmaf(a4.x, v0.x, acc0); acc1 = fmaf(a4.x, v0.y, acc1);
                acc2 = fmaf(a4.x, v0.z, acc2); acc3 = fmaf(a4.x, v0.w, acc3);
                acc0 = fmaf(a4.y, v1.x, acc0); acc1 = fmaf(a4.y, v1.y, acc1);
                acc2 = fmaf(a4.y, v1.z, acc2); acc3 = fmaf(a4.y, v1.w, acc3);
                acc0 = fmaf(a4.z, v2.x, acc0); acc1 = fmaf(a4.z, v2.y, acc1);
                acc2 = fmaf(a4.z, v2.z, acc2); acc3 = fmaf(a4.z, v2.w, acc3);
                acc0 = fmaf(a4.w, v3.x, acc0); acc1 = fmaf(a4.w, v3.y, acc1);
                acc2 = fmaf(a4.w, v3.z, acc2); acc3 = fmaf(a4.w, v3.w, acc3);
            }
            *(float4*)&o_g[(((long long)n * 4 + h) * 128 + q0 + r) * 32 + c0] =
                make_float4(acc0, acc1, acc2, acc3);
        }
    }
}

// =====================================================================
// K_out: per-atom [128x128]@[128x128] via mma.sync bf16 2-way split.
// =====================================================================
__global__ __launch_bounds__(256, 1)
void out_kernel(const float* __restrict__ b_out,
                float* __restrict__ out)
{
    extern __shared__ __nv_bfloat16 smb[];
    __nv_bfloat16* Ah = smb;
    __nv_bfloat16* Al = smb + 128 * LDA;
    __nv_bfloat16* Wh = smb + 2 * 128 * LDA;
    __nv_bfloat16* Wl = smb + 3 * 128 * LDA;

    const int n    = blockIdx.x;
    const int tid  = threadIdx.x;
    const int lane = tid & 31;
    const int wid  = tid >> 5;
    const int m2   = wid & 3;
    const int ng   = wid >> 2;
    const int mrow0 = m2 * 32;

    // stage O: logical O[i][j], j = h*32+d -> o_g[n*16384 + h*4096 + i*32 + d]
    const float* go = o_g + (long long)n * 16384;
    #pragma unroll
    for (int it = 0; it < 16; ++it) {
        int idx = it * 256 + tid;
        int i = idx >> 5, j4 = (idx & 31) * 4;
        int h = j4 >> 5, d = j4 & 31;
        float4 v = *(const float4*)(go + h * 4096 + i * 32 + d);
        __nv_bfloat16 h0 = __float2bfloat16_rn(v.x);
        __nv_bfloat16 h1 = __float2bfloat16_rn(v.y);
        __nv_bfloat16 h2 = __float2bfloat16_rn(v.z);
        __nv_bfloat16 h3 = __float2bfloat16_rn(v.w);
        *(__nv_bfloat162*)&Ah[i * LDA + j4]     = __halves2bfloat162(h0, h1);
        *(__nv_bfloat162*)&Ah[i * LDA + j4 + 2] = __halves2bfloat162(h2, h3);
        *(__nv_bfloat162*)&Al[i * LDA + j4] = __halves2bfloat162(
            __float2bfloat16_rn(v.x - __bfloat162float(h0)),
            __float2bfloat16_rn(v.y - __bfloat162float(h1)));
        *(__nv_bfloat162*)&Al[i * LDA + j4 + 2] = __halves2bfloat162(
            __float2bfloat16_rn(v.z - __bfloat162float(h2)),
            __float2bfloat16_rn(v.w - __bfloat162float(h3)));
    }
    #pragma unroll
    for (int it = 0; it < 8; ++it) {
        int idx = it * 256 + tid;
        int nn = idx >> 4, k8 = (idx & 15) * 8;
        *(float4*)&Wh[nn * LDA + k8] = *(const float4*)&wtout_h[nn * 128 + k8];
        *(float4*)&Wl[nn * LDA + k8] = *(const float4*)&wtout_l[nn * 128 + k8];
    }
    __syncthreads();

    const int r0 = lane >> 2;
    const int kp = (lane & 3) * 2;

    float acc[2][8][4];
    #pragma unroll
    for (int mi = 0; mi < 2; ++mi)
        #pragma unroll
        for (int nt = 0; nt < 8; ++nt)
            #pragma unroll
            for (int q = 0; q < 4; ++q) acc[mi][nt][q] = 0.f;

    #pragma unroll
    for (int k = 0; k < 8; ++k) {
        int k0 = k * 16 + kp;
        u32 ah[2][4], al[2][4];
        #pragma unroll
        for (int mi = 0; mi < 2; ++mi) {
            int r = mrow0 + mi * 16 + r0;
            ah[mi][0] = *(const u32*)&Ah[r * LDA + k0];
            ah[mi][1] = *(const u32*)&Ah[(r + 8) * LDA + k0];
            ah[mi][2] = *(const u32*)&Ah[r * LDA + k0 + 8];
            ah[mi][3] = *(const u32*)&Ah[(r + 8) * LDA + k0 + 8];
            al[mi][0] = *(const u32*)&Al[r * LDA + k0];
            al[mi][1] = *(const u32*)&Al[(r + 8) * LDA + k0];
            al[mi][2] = *(const u32*)&Al[r * LDA + k0 + 8];
            al[mi][3] = *(const u32*)&Al[(r + 8) * LDA + k0 + 8];
        }
        #pragma unroll
        for (int nt = 0; nt < 8; ++nt) {
            int ncol = ng * 64 + nt * 8 + r0;
            u32 bh0 = *(const u32*)&Wh[ncol * LDA + k0];
            u32 bh1 = *(const u32*)&Wh[ncol * LDA + k0 + 8];
            u32 bl0 = *(const u32*)&Wl[ncol * LDA + k0];
            u32 bl1 = *(const u32*)&Wl[ncol * LDA + k0 + 8];
            #pragma unroll
            for (int mi = 0; mi < 2; ++mi) {
                mma16816(acc[mi][nt], ah[mi], bh0, bh1);
                mma16816(acc[mi][nt], ah[mi], bl0, bl1);
                mma16816(acc[mi][nt], al[mi], bh0, bh1);
            }
        }
    }

    #pragma unroll
    for (int mi = 0; mi < 2; ++mi) {
        #pragma unroll
        for (int nt = 0; nt < 8; ++nt) {
            int gr = mrow0 + mi * 16 + r0;
            int gc = ng * 64 + nt * 8 + kp;
            float bo0 = b_out[gc], bo1 = b_out[gc + 1];
            float* dst = out + (long long)n * 16384;
            *(float2*)&dst[gr * 128 + gc] =
                make_float2(acc[mi][nt][0] + bo0, acc[mi][nt][1] + bo1);
            *(float2*)&dst[(gr + 8) * 128 + gc] =
                make_float2(acc[mi][nt][2] + bo0, acc[mi][nt][3] + bo1);
        }
    }
}

extern "C" void kernel_launch(void* const* d_in, const int* in_sizes, int n_in,
                              void* d_out, int out_size)
{
    const float* query   = (const float*)d_in[0];
    // d_in[1] = nei_mask (all True) — unused
    const float* input_r = (const float*)d_in[2];
    const float* sw      = (const float*)d_in[3];
    const float* s       = (const float*)d_in[4];
    const int*   atype   = (const int*)  d_in[5];
    const float* w_in    = (const float*)d_in[6];
    const float* b_in    = (const float*)d_in[7];
    const float* w_out   = (const float*)d_in[8];
    const float* b_out   = (const float*)d_in[9];
    const float* aew1    = (const float*)d_in[10];
    const float* aeb1    = (const float*)d_in[11];
    const float* aew2    = (const float*)d_in[12];
    const float* aeb2    = (const float*)d_in[13];
    const float* lng     = (const float*)d_in[14];
    const float* lnb     = (const float*)d_in[15];
    const float* ascale  = (const float*)d_in[16];
    float* outp = (float*)d_out;

    prep_kernel<<<256, 256>>>(w_in, w_out);
    bias_kernel<<<NATOMS, 256>>>(input_r, s, atype, aew1, aeb1, aew2, aeb2,
                                 lng, lnb, ascale);

    cudaFuncSetAttribute(qkv_kernel, cudaFuncAttributeMaxDynamicSharedMemorySize,
                         (int)GEMM_SMEM_BYTES);
    qkv_kernel<<<NATOMS, 256, GEMM_SMEM_BYTES>>>(query, b_in);

    cudaFuncSetAttribute(attn_kernel, cudaFuncAttributeMaxDynamicSharedMemorySize,
                         (int)ATTN_SMEM_BYTES);
    attn_kernel<<<NATOMS * HEADS, 128, ATTN_SMEM_BYTES>>>(sw, outp);

    cudaFuncSetAttribute(out_kernel, cudaFuncAttributeMaxDynamicSharedMemorySize,
                         (int)GEMM_SMEM_BYTES);
    out_kernel<<<NATOMS, 256, GEMM_SMEM_BYTES>>>(b_out, outp);
}